// round 1
// baseline (speedup 1.0000x reference)
#include <cuda_runtime.h>
#include <cstdint>

// Problem constants (fixed by the dataset)
#define M_DIM 8192      // BATCH*SEQ
#define N_DIM 4096      // OUT_DIM
#define K_DIM 4096      // IN_DIM
#define RANK  16

// Folded effective weight scratch (device global: allocation-free rule)
__device__ float g_weff[(size_t)N_DIM * K_DIM];

__device__ __forceinline__ float to_tf32(float x) {
    uint32_t u;
    asm("cvt.rna.tf32.f32 %0, %1;" : "=r"(u) : "f"(x));
    return __uint_as_float(u);
}

// ---------------------------------------------------------------------------
// Kernel 1: fold W_eff = W + (w1a@w1b) * (w2a@w2b) * scalar, pre-rounded tf32
// ---------------------------------------------------------------------------
__global__ void fold_kernel(const float* __restrict__ W,
                            const float* __restrict__ w1a,
                            const float* __restrict__ w1b,
                            const float* __restrict__ w2a,
                            const float* __restrict__ w2b,
                            const float* __restrict__ scalar) {
    int idx = blockIdx.x * 256 + threadIdx.x;       // over N*K = 16M elements
    int o = idx >> 12;                               // / 4096
    int i = idx & 4095;
    float s1 = 0.f, s2 = 0.f;
#pragma unroll
    for (int r = 0; r < RANK; ++r) {
        s1 += w1a[o * RANK + r] * w1b[r * K_DIM + i];
        s2 += w2a[o * RANK + r] * w2b[r * K_DIM + i];
    }
    float v = W[idx] + s1 * s2 * scalar[0];
    g_weff[idx] = to_tf32(v);                        // pre-round so GEMM skips cvt on B
}

// ---------------------------------------------------------------------------
// Kernel 2: y = x @ W_eff^T + bias   (tf32 mma.sync, 128x128x16 tiles)
// ---------------------------------------------------------------------------
#define BM 128
#define BN 128
#define BK 16
#define SSTRIDE (BK + 4)   // 20 floats: conflict-free fragment loads
#define NT (K_DIM / BK)    // 256 k-tiles

__global__ __launch_bounds__(256, 1)
void gemm_tf32_kernel(const float* __restrict__ X,
                      const float* __restrict__ bias,
                      float* __restrict__ Y) {
    __shared__ float sA[2][BM * SSTRIDE];
    __shared__ float sB[2][BN * SSTRIDE];

    const int bm = blockIdx.y, bn = blockIdx.x;
    const int tid  = threadIdx.x;
    const int warp = tid >> 5;
    const int lane = tid & 31;
    const int wm = warp & 1;        // 2 warps along M (64 rows each)
    const int wn = warp >> 1;       // 4 warps along N (32 cols each)
    const int g  = lane >> 2;       // group id 0..7
    const int t  = lane & 3;        // thread-in-group 0..3

    // gmem load mapping: 256 threads, each loads 2x float4 per matrix per tile
    const int lrow  = tid >> 2;          // 0..63
    const int lcol  = (tid & 3) * 4;     // 0,4,8,12
    const float* xg = X      + (size_t)(bm * BM + lrow) * K_DIM + lcol;
    const float* wg = g_weff + (size_t)(bn * BN + lrow) * K_DIM + lcol;

    float acc[4][4][4];
#pragma unroll
    for (int a = 0; a < 4; ++a)
#pragma unroll
        for (int b = 0; b < 4; ++b)
#pragma unroll
            for (int c = 0; c < 4; ++c) acc[a][b][c] = 0.f;

    float4 ra0, ra1, rb0, rb1;

    // --- load tile 0 ---
    ra0 = *(const float4*)(xg);
    ra1 = *(const float4*)(xg + (size_t)64 * K_DIM);
    rb0 = *(const float4*)(wg);
    rb1 = *(const float4*)(wg + (size_t)64 * K_DIM);
    {
        float4* pa0 = (float4*)&sA[0][lrow * SSTRIDE + lcol];
        float4* pa1 = (float4*)&sA[0][(lrow + 64) * SSTRIDE + lcol];
        *pa0 = make_float4(to_tf32(ra0.x), to_tf32(ra0.y), to_tf32(ra0.z), to_tf32(ra0.w));
        *pa1 = make_float4(to_tf32(ra1.x), to_tf32(ra1.y), to_tf32(ra1.z), to_tf32(ra1.w));
        *(float4*)&sB[0][lrow * SSTRIDE + lcol]        = rb0;   // already tf32-rounded
        *(float4*)&sB[0][(lrow + 64) * SSTRIDE + lcol] = rb1;
    }
    __syncthreads();

    for (int kt = 0; kt < NT; ++kt) {
        const int cur = kt & 1;
        const int nxt = cur ^ 1;

        // prefetch next tile gmem -> regs
        if (kt + 1 < NT) {
            const int k0 = (kt + 1) * BK;
            ra0 = *(const float4*)(xg + k0);
            ra1 = *(const float4*)(xg + (size_t)64 * K_DIM + k0);
            rb0 = *(const float4*)(wg + k0);
            rb1 = *(const float4*)(wg + (size_t)64 * K_DIM + k0);
        }

        // compute on smem[cur]
#pragma unroll
        for (int kk = 0; kk < BK; kk += 8) {
            uint32_t afr[4][4];
            uint32_t bfr[4][2];
#pragma unroll
            for (int mi = 0; mi < 4; ++mi) {
                const int m0 = wm * 64 + mi * 16;
                const float* base = &sA[cur][(m0 + g) * SSTRIDE + kk + t];
                afr[mi][0] = __float_as_uint(base[0]);
                afr[mi][1] = __float_as_uint(base[8 * SSTRIDE]);
                afr[mi][2] = __float_as_uint(base[4]);
                afr[mi][3] = __float_as_uint(base[8 * SSTRIDE + 4]);
            }
#pragma unroll
            for (int ni = 0; ni < 4; ++ni) {
                const int n0 = wn * 32 + ni * 8;
                const float* base = &sB[cur][(n0 + g) * SSTRIDE + kk + t];
                bfr[ni][0] = __float_as_uint(base[0]);
                bfr[ni][1] = __float_as_uint(base[4]);
            }
#pragma unroll
            for (int mi = 0; mi < 4; ++mi)
#pragma unroll
                for (int ni = 0; ni < 4; ++ni) {
                    asm volatile(
                        "mma.sync.aligned.m16n8k8.row.col.f32.tf32.tf32.f32 "
                        "{%0,%1,%2,%3}, {%4,%5,%6,%7}, {%8,%9}, {%0,%1,%2,%3};\n"
                        : "+f"(acc[mi][ni][0]), "+f"(acc[mi][ni][1]),
                          "+f"(acc[mi][ni][2]), "+f"(acc[mi][ni][3])
                        : "r"(afr[mi][0]), "r"(afr[mi][1]),
                          "r"(afr[mi][2]), "r"(afr[mi][3]),
                          "r"(bfr[ni][0]), "r"(bfr[ni][1]));
                }
        }

        // store prefetched tile into smem[nxt]
        if (kt + 1 < NT) {
            float4* pa0 = (float4*)&sA[nxt][lrow * SSTRIDE + lcol];
            float4* pa1 = (float4*)&sA[nxt][(lrow + 64) * SSTRIDE + lcol];
            *pa0 = make_float4(to_tf32(ra0.x), to_tf32(ra0.y), to_tf32(ra0.z), to_tf32(ra0.w));
            *pa1 = make_float4(to_tf32(ra1.x), to_tf32(ra1.y), to_tf32(ra1.z), to_tf32(ra1.w));
            *(float4*)&sB[nxt][lrow * SSTRIDE + lcol]        = rb0;
            *(float4*)&sB[nxt][(lrow + 64) * SSTRIDE + lcol] = rb1;
        }
        __syncthreads();
    }

    // epilogue: add bias, write out
#pragma unroll
    for (int mi = 0; mi < 4; ++mi) {
        const int row0 = bm * BM + wm * 64 + mi * 16 + g;
#pragma unroll
        for (int ni = 0; ni < 4; ++ni) {
            const int col = bn * BN + wn * 32 + ni * 8 + 2 * t;
            const float bv0 = __ldg(&bias[col]);
            const float bv1 = __ldg(&bias[col + 1]);
            Y[(size_t)row0 * N_DIM + col]           = acc[mi][ni][0] + bv0;
            Y[(size_t)row0 * N_DIM + col + 1]       = acc[mi][ni][1] + bv1;
            Y[(size_t)(row0 + 8) * N_DIM + col]     = acc[mi][ni][2] + bv0;
            Y[(size_t)(row0 + 8) * N_DIM + col + 1] = acc[mi][ni][3] + bv1;
        }
    }
}

// ---------------------------------------------------------------------------
extern "C" void kernel_launch(void* const* d_in, const int* in_sizes, int n_in,
                              void* d_out, int out_size) {
    const float* x      = (const float*)d_in[0];
    const float* W      = (const float*)d_in[1];
    const float* bias   = (const float*)d_in[2];
    const float* w1a    = (const float*)d_in[3];
    const float* w1b    = (const float*)d_in[4];
    const float* w2a    = (const float*)d_in[5];
    const float* w2b    = (const float*)d_in[6];
    const float* scalar = (const float*)d_in[7];
    float* y = (float*)d_out;

    fold_kernel<<<(N_DIM * K_DIM) / 256, 256>>>(W, w1a, w1b, w2a, w2b, scalar);

    dim3 grid(N_DIM / BN, M_DIM / BM);   // 32 x 64
    gemm_tf32_kernel<<<grid, 256>>>(x, bias, y);
}

// round 3
// speedup vs baseline: 2.5969x; 2.5969x over previous
#include <cuda_runtime.h>
#include <cuda_fp16.h>
#include <cstdint>

// Problem constants
#define M_DIM 8192
#define N_DIM 4096
#define K_DIM 4096
#define RANK  16

// GEMM tiling
#define BM 128
#define BN 256
#define BK 32                        // fp16 elems per k-tile
#define NT (K_DIM / BK)              // 128 k-iterations
#define NSTAGE 4
#define RS 40                        // smem row stride in halves (32 + 8 pad)
#define RSB (RS * 2)                 // 80 bytes
#define A_ST_BYTES (BM * RSB)        // 10240
#define B_ST_BYTES (BN * RSB)        // 20480
#define STAGE_BYTES (A_ST_BYTES + B_ST_BYTES)   // 30720
#define SMEM_TOTAL (NSTAGE * STAGE_BYTES)       // 122880

// Pre-converted fp16 operands (device globals: allocation-free rule)
__device__ __half g_xh[(size_t)M_DIM * K_DIM];
__device__ __half g_wh[(size_t)N_DIM * K_DIM];

// ---------------------------------------------------------------------------
// PTX helpers (all baseline ISA: sm_80/75, no 'a' features)
// ---------------------------------------------------------------------------
__device__ __forceinline__ uint32_t smem_to_u32(const void* p) {
    uint32_t a;
    asm("{ .reg .u64 t; cvta.to.shared.u64 t, %1; cvt.u32.u64 %0, t; }" : "=r"(a) : "l"(p));
    return a;
}
#define CP_ASYNC16(dst, src) \
    asm volatile("cp.async.cg.shared.global [%0], [%1], 16;" :: "r"(dst), "l"(src))
#define CP_COMMIT() asm volatile("cp.async.commit_group;")
#define CP_WAIT(n)  asm volatile("cp.async.wait_group %0;" :: "n"(n))

#define LDSM_X4(r, addr) \
    asm volatile("ldmatrix.sync.aligned.m8n8.x4.shared.b16 {%0,%1,%2,%3}, [%4];" \
                 : "=r"((r)[0]), "=r"((r)[1]), "=r"((r)[2]), "=r"((r)[3]) : "r"(addr))

#define MMA_F16(d, a, b0, b1) \
    asm volatile("mma.sync.aligned.m16n8k16.row.col.f32.f16.f16.f32 " \
                 "{%0,%1,%2,%3}, {%4,%5,%6,%7}, {%8,%9}, {%0,%1,%2,%3};" \
                 : "+f"((d)[0]), "+f"((d)[1]), "+f"((d)[2]), "+f"((d)[3]) \
                 : "r"((a)[0]), "r"((a)[1]), "r"((a)[2]), "r"((a)[3]), "r"(b0), "r"(b1))

// ---------------------------------------------------------------------------
// Kernel 0: convert x -> fp16
// ---------------------------------------------------------------------------
__global__ void convert_x_kernel(const float* __restrict__ x) {
    size_t i = (size_t)(blockIdx.x * 256 + threadIdx.x) * 4;
    float4 v = *(const float4*)(x + i);
    __half2* o = (__half2*)(g_xh + i);
    o[0] = __floats2half2_rn(v.x, v.y);
    o[1] = __floats2half2_rn(v.z, v.w);
}

// ---------------------------------------------------------------------------
// Kernel 1: fold W_eff = W + (w1a@w1b)*(w2a@w2b)*scalar -> fp16
// ---------------------------------------------------------------------------
__global__ void fold_kernel(const float* __restrict__ W,
                            const float* __restrict__ w1a,
                            const float* __restrict__ w1b,
                            const float* __restrict__ w2a,
                            const float* __restrict__ w2b,
                            const float* __restrict__ scalar) {
    size_t idx = (size_t)(blockIdx.x * 256 + threadIdx.x) * 4;
    int o = (int)(idx >> 12);
    int i = (int)(idx & 4095);
    float4 s1 = {0.f, 0.f, 0.f, 0.f};
    float4 s2 = {0.f, 0.f, 0.f, 0.f};
#pragma unroll
    for (int r = 0; r < RANK; ++r) {
        float a1 = w1a[o * RANK + r];
        float a2 = w2a[o * RANK + r];
        float4 b1 = *(const float4*)(w1b + (size_t)r * K_DIM + i);
        float4 b2 = *(const float4*)(w2b + (size_t)r * K_DIM + i);
        s1.x += a1 * b1.x; s1.y += a1 * b1.y; s1.z += a1 * b1.z; s1.w += a1 * b1.w;
        s2.x += a2 * b2.x; s2.y += a2 * b2.y; s2.z += a2 * b2.z; s2.w += a2 * b2.w;
    }
    float sc = scalar[0];
    float4 w = *(const float4*)(W + idx);
    __half2* out = (__half2*)(g_wh + idx);
    out[0] = __floats2half2_rn(w.x + s1.x * s2.x * sc, w.y + s1.y * s2.y * sc);
    out[1] = __floats2half2_rn(w.z + s1.z * s2.z * sc, w.w + s1.w * s2.w * sc);
}

// ---------------------------------------------------------------------------
// Kernel 2: Y[M,N] = Xh[M,K] @ Wh[N,K]^T + bias   (fp16 mma.sync, cp.async)
// Block 128x256, 8 warps, warp tile 64x64, 4-stage pipeline.
// ---------------------------------------------------------------------------
__global__ void __launch_bounds__(256, 1)
gemm_f16_kernel(const float* __restrict__ bias, float* __restrict__ Y) {
    extern __shared__ char smem[];
    const uint32_t sb0 = smem_to_u32(smem);
    const int tid = threadIdx.x;
    const int l = tid & 31;
    const int warp = tid >> 5;
    const int wm = warp & 1;     // 2 warps along M
    const int wn = warp >> 1;    // 4 warps along N

    // tile coords with 8-row supertile swizzle for L2 reuse
    const int bid = blockIdx.x;                 // 0..1023
    const int sbt = bid >> 7;
    const int rr = bid & 127;
    const int m0 = ((sbt << 3) + (rr & 7)) * BM;
    const int n0 = (rr >> 3) * BN;

    const __half* Xg = g_xh + (size_t)m0 * K_DIM;
    const __half* Wg = g_wh + (size_t)n0 * K_DIM;

    // gmem->smem cp.async mapping: thread -> (row, 16B chunk)
    const int arow = tid >> 2;           // 0..63
    const int achk = tid & 3;            // 0..3 (16B = 8 halves each)

    // ldmatrix lane address components
    const uint32_t lrow = l & 15;
    const uint32_t lkof = (uint32_t)(l >> 4) * 16;   // bytes (k8 half-tile)
    const uint32_t a_lane = (uint32_t)(wm * 64 + lrow) * RSB + lkof;
    const uint32_t b_lane = A_ST_BYTES + (uint32_t)(wn * 64 + lrow) * RSB + lkof;

    float acc[4][8][4];
#pragma unroll
    for (int a = 0; a < 4; ++a)
#pragma unroll
        for (int b = 0; b < 8; ++b)
#pragma unroll
            for (int c = 0; c < 4; ++c) acc[a][b][c] = 0.f;

    // ---- pipeline prologue ----
#pragma unroll
    for (int s = 0; s < NSTAGE - 1; ++s) {
        const uint32_t sa = sb0 + s * STAGE_BYTES;
        const __half* agp = Xg + (size_t)arow * K_DIM + s * BK + achk * 8;
#pragma unroll
        for (int i = 0; i < 2; ++i)
            CP_ASYNC16(sa + (uint32_t)(arow + i * 64) * RSB + achk * 16,
                       agp + (size_t)i * 64 * K_DIM);
        const __half* bgp = Wg + (size_t)arow * K_DIM + s * BK + achk * 8;
#pragma unroll
        for (int i = 0; i < 4; ++i)
            CP_ASYNC16(sa + A_ST_BYTES + (uint32_t)(arow + i * 64) * RSB + achk * 16,
                       bgp + (size_t)i * 64 * K_DIM);
        CP_COMMIT();
    }
    CP_WAIT(NSTAGE - 2);
    __syncthreads();

    // ---- main loop ----
    for (int kt = 0; kt < NT; ++kt) {
        const int cur = kt & (NSTAGE - 1);
        const int nk = kt + NSTAGE - 1;
        if (nk < NT) {
            const uint32_t sa = sb0 + (nk & (NSTAGE - 1)) * STAGE_BYTES;
            const __half* agp = Xg + (size_t)arow * K_DIM + nk * BK + achk * 8;
#pragma unroll
            for (int i = 0; i < 2; ++i)
                CP_ASYNC16(sa + (uint32_t)(arow + i * 64) * RSB + achk * 16,
                           agp + (size_t)i * 64 * K_DIM);
            const __half* bgp = Wg + (size_t)arow * K_DIM + nk * BK + achk * 8;
#pragma unroll
            for (int i = 0; i < 4; ++i)
                CP_ASYNC16(sa + A_ST_BYTES + (uint32_t)(arow + i * 64) * RSB + achk * 16,
                           bgp + (size_t)i * 64 * K_DIM);
        }
        CP_COMMIT();

        const uint32_t sa = sb0 + cur * STAGE_BYTES;
#pragma unroll
        for (int ks = 0; ks < 2; ++ks) {            // two k16 steps per BK=32
            uint32_t afr[4][4], bfr[4][4];
#pragma unroll
            for (int mi = 0; mi < 4; ++mi)
                LDSM_X4(afr[mi], sa + a_lane + (uint32_t)mi * 16 * RSB + ks * 32);
#pragma unroll
            for (int bi = 0; bi < 4; ++bi)
                LDSM_X4(bfr[bi], sa + b_lane + (uint32_t)bi * 16 * RSB + ks * 32);
#pragma unroll
            for (int mi = 0; mi < 4; ++mi)
#pragma unroll
                for (int bi = 0; bi < 4; ++bi) {
                    MMA_F16(acc[mi][2 * bi],     afr[mi], bfr[bi][0], bfr[bi][2]);
                    MMA_F16(acc[mi][2 * bi + 1], afr[mi], bfr[bi][1], bfr[bi][3]);
                }
        }
        CP_WAIT(NSTAGE - 2);
        __syncthreads();
    }

    // ---- epilogue: add bias, write fp32 ----
    const int g = l >> 2;
    const int t = l & 3;
#pragma unroll
    for (int mi = 0; mi < 4; ++mi) {
        const int row0 = m0 + wm * 64 + mi * 16 + g;
        float* y0 = Y + (size_t)row0 * N_DIM;
#pragma unroll
        for (int ni = 0; ni < 8; ++ni) {
            const int col = n0 + wn * 64 + (ni >> 1) * 16 + (ni & 1) * 8 + 2 * t;
            const float2 bv = *(const float2*)(bias + col);
            float2 o0, o1;
            o0.x = acc[mi][ni][0] + bv.x;  o0.y = acc[mi][ni][1] + bv.y;
            o1.x = acc[mi][ni][2] + bv.x;  o1.y = acc[mi][ni][3] + bv.y;
            *(float2*)(y0 + col) = o0;
            *(float2*)(y0 + (size_t)8 * N_DIM + col) = o1;   // rows g+8
        }
    }
}

// ---------------------------------------------------------------------------
extern "C" void kernel_launch(void* const* d_in, const int* in_sizes, int n_in,
                              void* d_out, int out_size) {
    const float* x      = (const float*)d_in[0];
    const float* W      = (const float*)d_in[1];
    const float* bias   = (const float*)d_in[2];
    const float* w1a    = (const float*)d_in[3];
    const float* w1b    = (const float*)d_in[4];
    const float* w2a    = (const float*)d_in[5];
    const float* w2b    = (const float*)d_in[6];
    const float* scalar = (const float*)d_in[7];
    float* y = (float*)d_out;

    convert_x_kernel<<<(int)(((size_t)M_DIM * K_DIM) / 4 / 256), 256>>>(x);
    fold_kernel<<<(int)(((size_t)N_DIM * K_DIM) / 4 / 256), 256>>>(W, w1a, w1b, w2a, w2b, scalar);

    cudaFuncSetAttribute(gemm_f16_kernel,
                         cudaFuncAttributeMaxDynamicSharedMemorySize, SMEM_TOTAL);
    const int nblocks = (M_DIM / BM) * (N_DIM / BN);   // 64 * 16 = 1024
    gemm_f16_kernel<<<nblocks, 256, SMEM_TOTAL>>>(bias, y);
}